// round 8
// baseline (speedup 1.0000x reference)
#include <cuda_runtime.h>
#include <cstdint>

// Problem constants
#define Nn   8192
#define Dd   256
#define Kk   32
#define GRID 152
#define TPB  512          // 16 warps; warp w owns d-slice [16w, 16w+16), lane = k
#define RI   8            // rows staged per chunk
#define NCH  (Nn / RI)    // 1024 chunks

// finalize tree
#define PG    8           // partial groups
#define PPG   19          // partials per group (8*19 = 152)

typedef unsigned long long ull;

// ---------- scratch (static device memory; no allocation) ----------
__device__ float g_part[GRID][2 * Kk * Dd];   // per-block partial G1|G2, [d][k] layout
__device__ float g_g0[GRID * Kk];             // per-block partial G0
__device__ float g_p2[PG][2 * Kk * Dd];       // stage-A reduced partials
__device__ float g_g02[PG * Kk];              // stage-A reduced G0

// ---------- packed f32x2 helpers ----------
__device__ __forceinline__ ull ffma2(ull a, ull b, ull c) {
    ull d;
    asm("fma.rn.f32x2 %0, %1, %2, %3;" : "=l"(d) : "l"(a), "l"(b), "l"(c));
    return d;
}
__device__ __forceinline__ ull fmul2(ull a, ull b) {
    ull d;
    asm("mul.rn.f32x2 %0, %1, %2;" : "=l"(d) : "l"(a), "l"(b));
    return d;
}
__device__ __forceinline__ ull fadd2(ull a, ull b) {
    ull d;
    asm("add.rn.f32x2 %0, %1, %2;" : "=l"(d) : "l"(a), "l"(b));
    return d;
}
__device__ __forceinline__ ull pack2(float lo, float hi) {
    ull r;
    asm("mov.b64 %0, {%1, %2};" : "=l"(r) : "f"(lo), "f"(hi));
    return r;
}
__device__ __forceinline__ void unpack2(ull v, float& lo, float& hi) {
    asm("mov.b64 {%0, %1}, %2;" : "=f"(lo), "=f"(hi) : "l"(v));
}

// ---------- main: software-pipelined fused kernel ----------
__global__ __launch_bounds__(TPB, 1) void main_kernel(const float* __restrict__ x,
                                                      const float* __restrict__ wg,
                                                      const float* __restrict__ bg) {
    __shared__ float xs[2][RI * Dd];       // 2 x 8 KB double-buffered rows
    __shared__ float red[RI * 16 * Kk];    // 16 KB logit partials [r][w][k]
    __shared__ float gam[2][RI * Kk];      // 2 x 1 KB gamma [r][k]
    __shared__ float es[Kk];

    const int t  = threadIdx.x;
    const int w  = t >> 5;     // warp id 0..15 -> d-slice
    const int k  = t & 31;     // lane -> mixture component
    const int d0 = w * 16;

    // ---- prologue: coefficient registers from w, b (red used as scratch)
    ull a2[8], c2[8];
    float pe = 0.0f;
    {
        const float4* w4 = reinterpret_cast<const float4*>(wg + k * Dd + d0);
        const float4* b4 = reinterpret_cast<const float4*>(bg + k * Dd + d0);
#pragma unroll
        for (int i = 0; i < 4; i++) {
            float4 wv = w4[i];
            float4 bv = b4[i];
            float w2x = wv.x * wv.x, w2y = wv.y * wv.y,
                  w2z = wv.z * wv.z, w2w = wv.w * wv.w;
            a2[2 * i]     = pack2(w2x - 1.0f, w2y - 1.0f);
            a2[2 * i + 1] = pack2(w2z - 1.0f, w2w - 1.0f);
            c2[2 * i]     = pack2(2.0f * w2x * bv.x, 2.0f * w2y * bv.y);
            c2[2 * i + 1] = pack2(2.0f * w2z * bv.z, 2.0f * w2w * bv.w);
            pe += w2x * bv.x * bv.x + w2y * bv.y * bv.y
                + w2z * bv.z * bv.z + w2w * bv.w * bv.w;
        }
    }
    red[w * Kk + k] = pe;
    __syncthreads();
    if (w == 0) {
        float s = 0.0f;
#pragma unroll
        for (int j = 0; j < 16; j++) s += red[j * Kk + k];
        es[k] = s;
    }

    ull acc1[8], acc2[8];
#pragma unroll
    for (int i = 0; i < 8; i++) { acc1[i] = 0ull; acc2[i] = 0ull; }
    float g0acc = 0.0f;

    const float4* xg = reinterpret_cast<const float4*>(x);

// phase A: logit partial = sum_{d in slice} (a*x + c)*x  over buffer BUF
#define PHASE_A(BUF)                                                          \
    {                                                                         \
        _Pragma("unroll")                                                     \
        for (int r = 0; r < RI; r++) {                                        \
            const float* xr = &xs[BUF][r * Dd + d0];                          \
            ull t0 = 0ull, t1 = 0ull;                                         \
            _Pragma("unroll")                                                 \
            for (int i = 0; i < 4; i++) {                                     \
                double2 v = *reinterpret_cast<const double2*>(xr + 4 * i);    \
                ull x0 = __double_as_longlong(v.x);                           \
                ull x1 = __double_as_longlong(v.y);                           \
                ull u0 = ffma2(a2[2 * i],     x0, c2[2 * i]);                 \
                ull u1 = ffma2(a2[2 * i + 1], x1, c2[2 * i + 1]);             \
                t0 = ffma2(u0, x0, t0);                                       \
                t1 = ffma2(u1, x1, t1);                                       \
            }                                                                 \
            float alo, ahi, blo, bhi;                                         \
            unpack2(t0, alo, ahi);                                            \
            unpack2(t1, blo, bhi);                                            \
            red[r * 512 + w * Kk + k] = (alo + ahi) + (blo + bhi);            \
        }                                                                     \
    }

// softmax for all RI rows of buffer SEL (warps 0..7, one row each)
#define SOFTMAX(SEL)                                                          \
    if (w < RI) {                                                             \
        int r = w;                                                            \
        float s = 0.0f;                                                       \
        _Pragma("unroll")                                                     \
        for (int j = 0; j < 16; j++) s += red[r * 512 + j * Kk + k];          \
        float lg = -0.5f * (s + es[k]);                                       \
        float m = lg;                                                         \
        _Pragma("unroll")                                                     \
        for (int o = 16; o > 0; o >>= 1)                                      \
            m = fmaxf(m, __shfl_xor_sync(0xffffffffu, m, o));                 \
        float p = __expf(lg - m);                                             \
        float sm = p;                                                         \
        _Pragma("unroll")                                                     \
        for (int o = 16; o > 0; o >>= 1)                                      \
            sm += __shfl_xor_sync(0xffffffffu, sm, o);                        \
        float g = p / sm;                                                     \
        gam[SEL][r * Kk + k] = g;                                             \
        g0acc += g;                                                           \
    }

// phase B: p = g*x; G1 += p; G2 += p*x  over buffer BUF with gamma set SEL
#define PHASE_B(BUF, SEL)                                                     \
    {                                                                         \
        _Pragma("unroll")                                                     \
        for (int r = 0; r < RI; r++) {                                        \
            float g = gam[SEL][r * Kk + k];                                   \
            ull gp = pack2(g, g);                                             \
            const float* xr = &xs[BUF][r * Dd + d0];                          \
            _Pragma("unroll")                                                 \
            for (int i = 0; i < 4; i++) {                                     \
                double2 v = *reinterpret_cast<const double2*>(xr + 4 * i);    \
                ull x0 = __double_as_longlong(v.x);                           \
                ull x1 = __double_as_longlong(v.y);                           \
                ull p0 = fmul2(gp, x0);                                       \
                ull p1 = fmul2(gp, x1);                                       \
                acc1[2 * i]     = fadd2(acc1[2 * i], p0);                     \
                acc1[2 * i + 1] = fadd2(acc1[2 * i + 1], p1);                 \
                acc2[2 * i]     = ffma2(p0, x0, acc2[2 * i]);                 \
                acc2[2 * i + 1] = ffma2(p1, x1, acc2[2 * i + 1]);             \
            }                                                                 \
        }                                                                     \
    }

    // ---- pipeline prologue
    int c = blockIdx.x;
    float4 r0 = xg[c * 512 + t];
    reinterpret_cast<float4*>(xs[0])[t] = r0;
    __syncthreads();                       // buf0 + es visible
    int cn = c + GRID;
    if (cn < NCH) r0 = xg[cn * 512 + t];   // prefetch chunk 1
    PHASE_A(0)
    __syncthreads();                       // red ready
    SOFTMAX(0)
    if (cn < NCH) reinterpret_cast<float4*>(xs[1])[t] = r0;
    __syncthreads();                       // gam[0] + buf1 ready

    // ---- steady state: A(cur) + B(prev) between syncs
    int pb = 0;
    for (c = cn; c < NCH; c += GRID) {
        int cnn = c + GRID;
        if (cnn < NCH) r0 = xg[cnn * 512 + t];   // prefetch next-next
        int cur = pb ^ 1;
        if (cur) { PHASE_A(1) } else { PHASE_A(0) }
        if (pb)  { PHASE_B(1, 1) } else { PHASE_B(0, 0) }
        __syncthreads();                   // red ready; buf[pb] free
        if (cur) { SOFTMAX(1) } else { SOFTMAX(0) }
        if (cnn < NCH) {
            if (pb) reinterpret_cast<float4*>(xs[1])[t] = r0;
            else    reinterpret_cast<float4*>(xs[0])[t] = r0;
        }
        __syncthreads();                   // gam[cur] + staged buf ready
        pb = cur;
    }
    // ---- drain: final B
    if (pb) { PHASE_B(1, 1) } else { PHASE_B(0, 0) }

    // ---- write per-block partials (coalesced: [d][k] layout)
    float* P = g_part[blockIdx.x];
#pragma unroll
    for (int i = 0; i < 8; i++) {
        float lo, hi;
        unpack2(acc1[i], lo, hi);
        P[(d0 + 2 * i) * Kk + k]     = lo;
        P[(d0 + 2 * i + 1) * Kk + k] = hi;
        unpack2(acc2[i], lo, hi);
        P[8192 + (d0 + 2 * i) * Kk + k]     = lo;
        P[8192 + (d0 + 2 * i + 1) * Kk + k] = hi;
    }

    // ---- G0 partial: warps 0..7 hold lane-k gamma sums
    __syncthreads();
    if (w < RI) red[w * Kk + k] = g0acc;
    __syncthreads();
    if (w == 0) {
        float s = 0.0f;
#pragma unroll
        for (int j = 0; j < RI; j++) s += red[j * Kk + k];
        g_g0[blockIdx.x * Kk + k] = s;
    }
#undef PHASE_A
#undef SOFTMAX
#undef PHASE_B
}

// ---------- stage A: 152 -> 8 partials, massively parallel ----------
__global__ __launch_bounds__(256) void reduceA_kernel() {
    const int g   = blockIdx.x >> 4;          // group 0..7
    const int blk = blockIdx.x & 15;          // 0..15
    const int j4  = blk * 256 + threadIdx.x;  // float4 index 0..4095
    const int p0  = g * PPG;

    float4 s = make_float4(0.f, 0.f, 0.f, 0.f);
#pragma unroll
    for (int i = 0; i < PPG; i++) {
        const float4 v = reinterpret_cast<const float4*>(g_part[p0 + i])[j4];
        s.x += v.x; s.y += v.y; s.z += v.z; s.w += v.w;
    }
    reinterpret_cast<float4*>(g_p2[g])[j4] = s;

    if (blk == 0 && threadIdx.x < Kk) {
        float t = 0.0f;
#pragma unroll
        for (int i = 0; i < PPG; i++) t += g_g0[(p0 + i) * Kk + threadIdx.x];
        g_g02[g * Kk + threadIdx.x] = t;
    }
}

// ---------- stage B: 8 -> 1 + epilogue transform ----------
__global__ __launch_bounds__(256) void reduceB_kernel(const float* __restrict__ w,
                                                      const float* __restrict__ b,
                                                      float* __restrict__ out) {
    __shared__ float sG0[Kk];
    int t = threadIdx.x;
    if (t < Kk) {
        float s = 0.0f;
#pragma unroll
        for (int g = 0; g < PG; g++) s += g_g02[g * Kk + t];
        sG0[t] = s;
    }
    __syncthreads();

    int e = blockIdx.x * 256 + t;   // 0..8191, e = d*32 + k
    int d = e >> 5;
    int k = e & 31;

    float s1 = 0.0f, s2 = 0.0f;
#pragma unroll
    for (int g = 0; g < PG; g++) {
        s1 += g_p2[g][e];
        s2 += g_p2[g][8192 + e];
    }

    float wv = w[k * Dd + d];
    float bv = b[k * Dd + d];
    float G0 = sG0[k];
    const float invN = 1.0f / (float)Nn;

    float mu = wv * (s1 + bv * G0) * invN;
    float w2 = wv * wv;
    float m2 = w2 * (s2 + 2.0f * bv * s1 + bv * bv * G0);
    float sig = (m2 - G0) * (invN * 0.70710678118654752440f);

    out[k * Dd + d]        = sig;   // sigma part
    out[8192 + k * Dd + d] = mu;    // mu part
}

extern "C" void kernel_launch(void* const* d_in, const int* in_sizes, int n_in,
                              void* d_out, int out_size) {
    const float* x = (const float*)d_in[0];
    const float* w = (const float*)d_in[1];
    const float* b = (const float*)d_in[2];
    float* out = (float*)d_out;

    main_kernel<<<GRID, TPB>>>(x, w, b);
    reduceA_kernel<<<PG * 16, 256>>>();
    reduceB_kernel<<<32, 256>>>(w, b, out);
}